// round 8
// baseline (speedup 1.0000x reference)
#include <cuda_runtime.h>
#include <math.h>

#define Bsz    2048
#define Hd     256
#define INd    64
#define KTERMS 8
#define ROWS   8
#define NCTAS  256
#define NTHR   256
#define PITCH  12          // floats per smem act row (48B, odd 16B-granule stride)
#define SLOT   18          // u64 per export slot (144B, odd 16B-granule stride)

typedef unsigned long long ull;

// Pre-transposed weights (L2-resident)
__device__ float g_whT[Hd*Hd];     // whT[j*Hd+k]   = wh[k*Hd+j]
__device__ float g_woutT[Hd*Hd];   // woutT[j*Hd+k] = wout[k*Hd+j]
__device__ float g_wxT[INd*Hd];    // wxT[i*Hd+k]   = wx[k*INd+i]

// ---------------- packed f32x2 helpers ----------------
__device__ __forceinline__ ull pack2(float lo, float hi) {
    ull r; asm("mov.b64 %0, {%1,%2};" : "=l"(r) : "f"(lo), "f"(hi)); return r;
}
__device__ __forceinline__ void unpack2(ull v, float& lo, float& hi) {
    asm("mov.b64 {%0,%1}, %2;" : "=f"(lo), "=f"(hi) : "l"(v));
}
__device__ __forceinline__ ull fma2(ull a, ull b, ull c) {
    ull d; asm("fma.rn.f32x2 %0, %1, %2, %3;" : "=l"(d) : "l"(a), "l"(b), "l"(c)); return d;
}
__device__ __forceinline__ ull mul2(ull a, ull b) {
    ull d; asm("mul.rn.f32x2 %0, %1, %2;" : "=l"(d) : "l"(a), "l"(b)); return d;
}
__device__ __forceinline__ ull add2(ull a, ull b) {
    ull d; asm("add.rn.f32x2 %0, %1, %2;" : "=l"(d) : "l"(a), "l"(b)); return d;
}
__device__ __forceinline__ void barg(int id) {
    asm volatile("bar.sync %0, 64;" :: "r"(id) : "memory");
}

struct Row4 { ull v[4]; };
__device__ __forceinline__ Row4 ldrow4(const float* p) {
    Row4 r;
    const ulonglong2* q = reinterpret_cast<const ulonglong2*>(p);
    ulonglong2 a = q[0], b = q[1];
    r.v[0]=a.x; r.v[1]=a.y; r.v[2]=b.x; r.v[3]=b.y;
    return r;
}

// Group g handles j = g + 4m (m = 0..NJ-1). phys(j) = (j>>2) + (j&3)*BLK = m + BLK*g.
// Single-act gemm: acc[c*4+t] += Wt[j][col0+c] * sIn[m + BLK*g][t]
template<int NJ, int BLK>
__device__ __forceinline__ void gemm1(const float* __restrict__ Wt, int col0, int g,
                                      const float* sIn, ull acc[16]) {
    const float* wp = Wt + g * Hd + col0;
    const float* sp = sIn + (BLK * g) * PITCH;
#pragma unroll 8
    for (int m = 0; m < NJ; ++m) {
        float4 w4 = *reinterpret_cast<const float4*>(wp);
        Row4 v = ldrow4(sp);
        ull w0 = pack2(w4.x, w4.x), w1 = pack2(w4.y, w4.y);
        ull w2 = pack2(w4.z, w4.z), w3 = pack2(w4.w, w4.w);
#pragma unroll
        for (int t = 0; t < 4; ++t) {
            acc[t]    = fma2(w0, v.v[t], acc[t]);
            acc[4+t]  = fma2(w1, v.v[t], acc[4+t]);
            acc[8+t]  = fma2(w2, v.v[t], acc[8+t]);
            acc[12+t] = fma2(w3, v.v[t], acc[12+t]);
        }
        wp += 4 * Hd;
        sp += PITCH;
    }
}

// Dual-act gemm: shared weights, two activation arrays, two accumulator sets.
template<int NJ, int BLK>
__device__ __forceinline__ void gemm_dual(const float* __restrict__ Wt, int col0, int g,
                                          const float* sIn1, const float* sIn2,
                                          ull acc1[16], ull acc2[16]) {
    const float* wp  = Wt + g * Hd + col0;
    const float* sp1 = sIn1 + (BLK * g) * PITCH;
    const float* sp2 = sIn2 + (BLK * g) * PITCH;
#pragma unroll 4
    for (int m = 0; m < NJ; ++m) {
        float4 w4 = *reinterpret_cast<const float4*>(wp);
        Row4 v1 = ldrow4(sp1);
        Row4 v2 = ldrow4(sp2);
        ull w0 = pack2(w4.x, w4.x), w1 = pack2(w4.y, w4.y);
        ull w2 = pack2(w4.z, w4.z), w3 = pack2(w4.w, w4.w);
#pragma unroll
        for (int t = 0; t < 4; ++t) {
            acc1[t]    = fma2(w0, v1.v[t], acc1[t]);
            acc1[4+t]  = fma2(w1, v1.v[t], acc1[4+t]);
            acc1[8+t]  = fma2(w2, v1.v[t], acc1[8+t]);
            acc1[12+t] = fma2(w3, v1.v[t], acc1[12+t]);
            acc2[t]    = fma2(w0, v2.v[t], acc2[t]);
            acc2[4+t]  = fma2(w1, v2.v[t], acc2[4+t]);
            acc2[8+t]  = fma2(w2, v2.v[t], acc2[8+t]);
            acc2[12+t] = fma2(w3, v2.v[t], acc2[12+t]);
        }
        wp += 4 * Hd;
        sp1 += PITCH;
        sp2 += PITCH;
    }
}

// export 16 u64 to slot (8 STS.128)
__device__ __forceinline__ void exportP(ull* p, const ull acc[16]) {
    ulonglong2* q = reinterpret_cast<ulonglong2*>(p);
#pragma unroll
    for (int c = 0; c < 8; ++c) q[c] = make_ulonglong2(acc[2*c], acc[2*c+1]);
}

// merge column (offset g*4 within each group's slot at this quad) across 4 groups
__device__ __forceinline__ void mergeP(const ull* buf, int quad, int g, ull m[4]) {
    m[0] = m[1] = m[2] = m[3] = 0ull;
#pragma unroll
    for (int gp = 0; gp < 4; ++gp) {
        const ull* p = buf + (gp * 64 + quad) * SLOT + g * 4;
        ulonglong2 a = reinterpret_cast<const ulonglong2*>(p)[0];
        ulonglong2 b = reinterpret_cast<const ulonglong2*>(p)[1];
        m[0] = add2(m[0], a.x); m[1] = add2(m[1], a.y);
        m[2] = add2(m[2], b.x); m[3] = add2(m[3], b.y);
    }
}

__device__ __forceinline__ void st_slice(float* rowbase, const ull m[4]) {
    ulonglong2* p = reinterpret_cast<ulonglong2*>(rowbase);
    p[0] = make_ulonglong2(m[0], m[1]);
    p[1] = make_ulonglong2(m[2], m[3]);
}

// ---------------- merged transpose ----------------
__global__ void transpose_all(const float* __restrict__ wh,
                              const float* __restrict__ wout,
                              const float* __restrict__ wx) {
    __shared__ float tile[32][33];
    int b = blockIdx.x;
    const float* in; float* out; int rows, cols, bx;
    if (b < 64)       { in = wh;   out = g_whT;   rows = Hd; cols = Hd;  bx = b; }
    else if (b < 128) { in = wout; out = g_woutT; rows = Hd; cols = Hd;  bx = b - 64; }
    else              { in = wx;   out = g_wxT;   rows = Hd; cols = INd; bx = b - 128; }
    int nbx = cols / 32;
    int c0 = (bx % nbx) * 32, r0 = (bx / nbx) * 32;
    for (int dy = threadIdx.y; dy < 32; dy += 8)
        tile[dy][threadIdx.x] = in[(r0 + dy) * cols + (c0 + threadIdx.x)];
    __syncthreads();
    for (int dy = threadIdx.y; dy < 32; dy += 8)
        out[(c0 + dy) * rows + (r0 + threadIdx.x)] = tile[threadIdx.x][dy];
}

// ---------------- fused vector-field kernel (2 CTAs / SM) ----------------
__global__ void __launch_bounds__(NTHR, 2)
fused_kernel(const float* __restrict__ hin, const float* __restrict__ xin,
             const float* __restrict__ xdin, const float* __restrict__ b0,
             const float* __restrict__ b1, float* __restrict__ out) {
    extern __shared__ __align__(16) char smraw[];
    ull*   sRed0 = reinterpret_cast<ull*>(smraw);                 // [256][SLOT] 36864B
    ull*   sRed1 = sRed0 + NTHR * SLOT;                           // [256][SLOT] 36864B
    float* sA    = reinterpret_cast<float*>(sRed1 + NTHR * SLOT); // [256][PITCH] 12288B
    float* sB    = sA + Hd * PITCH;                               // [256][PITCH] 12288B
    float* sXx   = sB + Hd * PITCH;                               // [64][PITCH]  3072B
    float* sXd   = sXx + INd * PITCH;                             // [64][PITCH]  3072B

    const int tid   = threadIdx.x;
    const int warp  = tid >> 5;
    const int lane  = tid & 31;
    const int g     = warp >> 1;                 // j-class: handles j ≡ g (mod 4)
    const int quad  = ((warp & 1) << 5) + lane;  // 0..63
    const int col0  = quad << 2;
    const int mycol = col0 + g;
    const int myrow = quad + (g << 6);           // phys(mycol) ∈ group g's read range
    ull* slot0 = sRed0 + (g * 64 + quad) * SLOT;
    ull* slot1 = sRed1 + (g * 64 + quad) * SLOT;
    const int row0  = blockIdx.x * ROWS;

    // ---- stage inputs (transposed + phys-permuted); 2048 = 256*8, no tail
    for (int e = tid; e < ROWS * Hd; e += NTHR) {
        int r = e >> 8, j = e & 255;
        int pr = (j >> 2) + ((j & 3) << 6);
        sA[pr * PITCH + r] = hin[(row0 + r) * Hd + j];
    }
    for (int e = tid; e < ROWS * INd; e += NTHR) {
        int r = e >> 6, i = e & 63;
        int pr = (i >> 2) + ((i & 3) << 4);
        sXx[pr * PITCH + r] = xin[(row0 + r) * INd + i];
        sXd[pr * PITCH + r] = xdin[(row0 + r) * INd + i];
    }
    __syncthreads();

    ull gate[4], dth[4], hd[4];
    ull acc1[16], acc2[16];

    // ---- P12 (fused): l1 = x@wxT + h@whT + b0 ; uu = xdot@wxT
#pragma unroll
    for (int q = 0; q < 16; ++q) { acc1[q] = 0ull; acc2[q] = 0ull; }
    gemm_dual<16, 16>(g_wxT, col0, g, sXx, sXd, acc1, acc2);
    gemm1<64, 64>(g_whT, col0, g, sA, acc1);
    exportP(slot0, acc1);
    exportP(slot1, acc2);
    __syncthreads();
    {
        ull m1[4], m2[4];
        mergeP(sRed0, quad, g, m1);
        mergeP(sRed1, quad, g, m2);
        float bk = b0[mycol];
        ull bp = pack2(bk, bk);
        ull relu[4], gu[4];
#pragma unroll
        for (int t = 0; t < 4; ++t) {
            m1[t] = add2(m1[t], bp);
            float a, b; unpack2(m1[t], a, b);
            float ga = (a > 0.f) ? 1.f : 0.f;
            float gb = (b > 0.f) ? 1.f : 0.f;
            gate[t] = pack2(ga, gb);
            relu[t] = pack2(ga * a, gb * b);
            gu[t]   = mul2(m2[t], gate[t]);
        }
        st_slice(sB + myrow * PITCH, relu);   // relu -> sB (h in sA now dead)
        st_slice(sA + myrow * PITCH, gu);     // gated-u -> sA
    }
    __syncthreads();   // buffer-reuse safety before dual re-export

    // ---- P34 (fused): lout = relu@woutT + b1 ; jx = gated-u@woutT
#pragma unroll
    for (int q = 0; q < 16; ++q) { acc1[q] = 0ull; acc2[q] = 0ull; }
    gemm_dual<64, 64>(g_woutT, col0, g, sB, sA, acc1, acc2);
    exportP(slot0, acc1);
    exportP(slot1, acc2);
    __syncthreads();
    {
        ull m1[4], m2[4];
        mergeP(sRed0, quad, g, m1);
        mergeP(sRed1, quad, g, m2);
        float bk = b1[mycol];
        ull bp = pack2(bk, bk);
        ull cur[4];
#pragma unroll
        for (int t = 0; t < 4; ++t) {
            ull L = add2(m1[t], bp);
            float a, b; unpack2(L, a, b);
            float ta = tanhf(a), tb = tanhf(b);
            dth[t] = pack2(1.f - ta * ta, 1.f - tb * tb);
            cur[t] = mul2(m2[t], dth[t]);
            hd[t]  = cur[t];
        }
        st_slice(sA + myrow * PITCH, cur);    // curr -> sA
    }
    __syncthreads();   // buffer-reuse safety before iterations

    // ---- 8 Jh-power iterations: curr = dth * ((gate * (curr@whT)) @ woutT)
    for (int it = 0; it < KTERMS; ++it) {
#pragma unroll
        for (int q = 0; q < 16; ++q) acc1[q] = 0ull;
        gemm1<64, 64>(g_whT, col0, g, sA, acc1);
        exportP(slot0, acc1);
        __syncthreads();
        {
            ull m[4];
            mergeP(sRed0, quad, g, m);
#pragma unroll
            for (int t = 0; t < 4; ++t) m[t] = mul2(m[t], gate[t]);
            st_slice(sB + myrow * PITCH, m);
        }
        barg(g + 1);    // group-local: only group g reads rows [64g,64g+64)
#pragma unroll
        for (int q = 0; q < 16; ++q) acc1[q] = 0ull;
        gemm1<64, 64>(g_woutT, col0, g, sB, acc1);
        exportP(slot1, acc1);
        __syncthreads();
        {
            ull m[4];
            mergeP(sRed1, quad, g, m);
#pragma unroll
            for (int t = 0; t < 4; ++t) {
                m[t] = mul2(m[t], dth[t]);
                hd[t] = add2(hd[t], m[t]);
            }
            st_slice(sA + myrow * PITCH, m);
        }
        barg(g + 1);
    }

    // ---- write h_dot: thread owns (mycol, rows row0..row0+7)
#pragma unroll
    for (int t = 0; t < 4; ++t) {
        float a, b; unpack2(hd[t], a, b);
        out[(row0 + 2*t)     * Hd + mycol] = a;
        out[(row0 + 2*t + 1) * Hd + mycol] = b;
    }
}

#define SMEM_BYTES (2 * NTHR * SLOT * 8 + (2 * Hd + 2 * INd) * PITCH * 4)

extern "C" void kernel_launch(void* const* d_in, const int* in_sizes, int n_in,
                              void* d_out, int out_size) {
    (void)in_sizes; (void)n_in; (void)out_size;
    const float* h_   = (const float*)d_in[0];
    const float* x    = (const float*)d_in[1];
    const float* xdot = (const float*)d_in[2];
    const float* wx   = (const float*)d_in[3];
    const float* wh   = (const float*)d_in[4];
    const float* wout = (const float*)d_in[5];
    const float* b0   = (const float*)d_in[6];
    const float* b1   = (const float*)d_in[7];
    float* out = (float*)d_out;

    cudaFuncSetAttribute(fused_kernel, cudaFuncAttributeMaxDynamicSharedMemorySize, SMEM_BYTES);
    transpose_all<<<144, dim3(32, 8)>>>(wh, wout, wx);
    fused_kernel<<<NCTAS, NTHR, SMEM_BYTES>>>(h_, x, xdot, b0, b1, out);
}